// round 9
// baseline (speedup 1.0000x reference)
#include <cuda_runtime.h>
#include <cuda_bf16.h>
#include <stdint.h>

// ---------------------------------------------------------------------------
// CubeMoveHead R8: select-then-MLP, both layers on mma.sync.m16n8k16 bf16
// (3-pass hi/lo split). One CTA per batch (64 slots), 8 warps:
//   - select: all 8 warps, 256-wide strips, block-prefix ranks
//   - layer1: warp tile = 16 slots x 64 h (warp pairs split the h dim)
//   - layer2: partial per warp over its 64 h, pair-reduced via smem
// Weights pre-arranged in HMMA fragment order by k_prep.
// ---------------------------------------------------------------------------

#define D 128
#define G 128
#define H 128
#define MC 64
#define MV 24
#define NEGV (-1000000000.0f)
#define MAXB 1024

__device__ int   g_segStart[MAXB + 1];
__device__ int   g_maskIsBool[2];       // [0] cube_mask, [1] move_mask
__device__ float g_hg[MAXB * H];        // gf[b] @ W1[D:,:] + b1
__device__ uint4 g_b1frag[4096];        // W1[:D,:] frags [kc8][nt16][lane32]{bhi0,bhi1,blo0,blo1}
__device__ uint4 g_b2frag[768];         // W2 frags [kc8][nt3][lane32]

// ---------------------------------------------------------------------------
__device__ __forceinline__ uint32_t pkbf(float lo, float hi) {
    unsigned short l = __bfloat16_as_ushort(__float2bfloat16(lo));
    unsigned short h = __bfloat16_as_ushort(__float2bfloat16(hi));
    return (uint32_t)l | ((uint32_t)h << 16);
}
__device__ __forceinline__ float bfres(float x) {
    return x - __bfloat162float(__float2bfloat16(x));
}
__device__ __forceinline__ void mma16816(float* c, uint32_t a0, uint32_t a1,
                                         uint32_t a2, uint32_t a3,
                                         uint32_t b0, uint32_t b1) {
    asm volatile(
        "mma.sync.aligned.m16n8k16.row.col.f32.bf16.bf16.f32 "
        "{%0,%1,%2,%3}, {%4,%5,%6,%7}, {%8,%9}, {%0,%1,%2,%3};"
        : "+f"(c[0]), "+f"(c[1]), "+f"(c[2]), "+f"(c[3])
        : "r"(a0), "r"(a1), "r"(a2), "r"(a3), "r"(b0), "r"(b1));
}

// ---------------------------------------------------------------------------
// k_prep: block 0 = dtype detect; blocks 1..B = per-batch hg; next 16 = W1
// fragment build; next = W2 fragment build; last = segment starts.
// ---------------------------------------------------------------------------
__global__ __launch_bounds__(256) void k_prep(
    const float* __restrict__ gf, const float* __restrict__ W1,
    const float* __restrict__ b1, const float* __restrict__ W2,
    const unsigned char* __restrict__ cm, const unsigned char* __restrict__ mv,
    const int* __restrict__ batch, int n, int B) {
    int bid = blockIdx.x, tid = threadIdx.x;

    if (bid == 0) {
        int f0 = 0, f1 = 0;
        for (int i = tid; i < 4096; i += 256)
            if (i & 3) { f0 |= cm[i]; f1 |= mv[i]; }
        int r0 = __syncthreads_or(f0);
        int r1 = __syncthreads_or(f1);
        if (tid == 0) { g_maskIsBool[0] = (r0 != 0); g_maskIsBool[1] = (r1 != 0); }
    } else if (bid <= B) {
        __shared__ float s_g[G];
        int b = bid - 1;
        if (tid < G) s_g[tid] = gf[b * G + tid];
        __syncthreads();
        if (tid < H) {
            float a = b1[tid];
#pragma unroll 4
            for (int k = 0; k < G; k++)
                a = fmaf(s_g[k], W1[(D + k) * H + tid], a);
            g_hg[b * H + tid] = a;
        }
    } else {
        int rel = bid - B - 1;
        if (rel < 16) {
            int idx = rel * 256 + tid;          // 0..4095
            int lane = idx & 31, nt = (idx >> 5) & 15, kc = idx >> 9;
            int nn = nt * 8 + (lane >> 2);
            int k0 = kc * 16 + (lane & 3) * 2;
            float w00 = W1[(k0 + 0) * H + nn], w01 = W1[(k0 + 1) * H + nn];
            float w10 = W1[(k0 + 8) * H + nn], w11 = W1[(k0 + 9) * H + nn];
            uint4 o;
            o.x = pkbf(w00, w01);
            o.y = pkbf(w10, w11);
            o.z = pkbf(bfres(w00), bfres(w01));
            o.w = pkbf(bfres(w10), bfres(w11));
            g_b1frag[idx] = o;
        } else if (rel == 16) {
            for (int idx = tid; idx < 768; idx += 256) {
                int kc = idx / 96, r = idx % 96, nt = r >> 5, lane = r & 31;
                int nn = nt * 8 + (lane >> 2);
                int k0 = kc * 16 + (lane & 3) * 2;
                float w00 = W2[(k0 + 0) * MV + nn], w01 = W2[(k0 + 1) * MV + nn];
                float w10 = W2[(k0 + 8) * MV + nn], w11 = W2[(k0 + 9) * MV + nn];
                uint4 o;
                o.x = pkbf(w00, w01);
                o.y = pkbf(w10, w11);
                o.z = pkbf(bfres(w00), bfres(w01));
                o.w = pkbf(bfres(w10), bfres(w11));
                g_b2frag[idx] = o;
            }
        } else {
            for (int v = tid; v <= B; v += 256) {
                int lo = 0, hi = n;
                while (lo < hi) {
                    int mid = (lo + hi) >> 1;
                    if (batch[mid] < v) lo = mid + 1; else hi = mid;
                }
                g_segStart[v] = lo;
            }
        }
    }
}

// ---------------------------------------------------------------------------
// k_mlp: one CTA = one batch = 64 slots, 256 threads (8 warps).
// ---------------------------------------------------------------------------
#define ALD 68                    // row stride (uint32) for packed A: 32 + 36pad? (34 used, 68 words)
#define AHI_BYTES (64 * ALD * 4)  // 17408
#define DSMEM_BYTES (2 * AHI_BYTES)

__global__ __launch_bounds__(256) void k_mlp(
    const float* __restrict__ nf, const float* __restrict__ b2,
    const unsigned char* __restrict__ cmb, const int* __restrict__ cmi,
    const unsigned char* __restrict__ mvb, const int* __restrict__ mvi,
    float* __restrict__ out) {
    extern __shared__ unsigned char dsm[];
    uint32_t* s_ahi = (uint32_t*)dsm;                 // [64][ALD] bf16-hi pairs
    uint32_t* s_alo = (uint32_t*)(dsm + AHI_BYTES);   // [64][ALD] lo pairs
    __shared__ float s_hg[H];
    __shared__ float s_b2[MV];
    __shared__ int   s_sel[MC];
    __shared__ int   s_wcnt[8];
    __shared__ int   s_base;
    __shared__ float s_red[4 * 32 * 12];              // layer-2 pair reduction (6KB)

    int tid = threadIdx.x, lane = tid & 31, w = tid >> 5;
    int b = blockIdx.x;
    int isb = g_maskIsBool[0], isb2 = g_maskIsBool[1];

    if (tid < H) s_hg[tid] = g_hg[b * H + tid];
    if (tid < MV) s_b2[tid] = b2[tid];
    if (tid == 0) s_base = 0;
    __syncthreads();

    // ---- select: 256-wide strips, block prefix, early exit ----
    {
        int start = g_segStart[b], end = g_segStart[b + 1];
        for (int it = start; it < end; it += 256) {
            if (s_base >= MC) break;     // uniform (post-sync shared value)
            int i = it + tid;
            int c = 0;
            if (i < end) c = isb ? (cmb[i] != 0) : (cmi[i] != 0);
            unsigned mm = __ballot_sync(0xffffffffu, c);
            if (lane == 0) s_wcnt[w] = __popc(mm);
            __syncthreads();
            int pre = 0, tot = 0;
#pragma unroll
            for (int ww = 0; ww < 8; ww++) {
                int v = s_wcnt[ww];
                if (ww < w) pre += v;
                tot += v;
            }
            if (c) {
                int rank = s_base + pre + __popc(mm & ((1u << lane) - 1u));
                if (rank < MC) s_sel[rank] = i;
            }
            __syncthreads();
            if (tid == 0) s_base += tot;
            __syncthreads();
        }
    }
    int vc = (s_base < MC) ? s_base : MC;

    // ---- gather node features -> packed bf16 hi/lo in smem ----
    for (int i = tid; i < 2048; i += 256) {      // 64 slots x 32 float4
        int s = i >> 5, q = i & 31;
        float4 v = make_float4(0.f, 0.f, 0.f, 0.f);
        if (s < vc) {
            long long node = s_sel[s];
            v = *(const float4*)&nf[node * D + q * 4];
        }
        uint2 hi, lo;
        hi.x = pkbf(v.x, v.y);               hi.y = pkbf(v.z, v.w);
        lo.x = pkbf(bfres(v.x), bfres(v.y)); lo.y = pkbf(bfres(v.z), bfres(v.w));
        *(uint2*)&s_ahi[s * ALD + q * 2] = hi;
        *(uint2*)&s_alo[s * ALD + q * 2] = lo;
    }
    __syncthreads();

    // ---- layer 1: warp tile = 16 slots x 64 h (3-pass bf16 HMMA) ----
    int wq = w & 3;                 // slot quarter
    int hh = w >> 2;                // h half (0: h0..63, 1: h64..127)
    int hb = hh * 8;                // nt offset into b1frag
    int r1 = wq * 16 + (lane >> 2);
    int jb = lane & 3;

    float acc[8][4];
#pragma unroll
    for (int nt = 0; nt < 8; nt++)
#pragma unroll
        for (int j = 0; j < 4; j++) acc[nt][j] = 0.f;

#pragma unroll 1
    for (int kc = 0; kc < 8; kc++) {
        int j0 = kc * 8 + jb;
        uint32_t ah0 = s_ahi[r1 * ALD + j0];
        uint32_t ah1 = s_ahi[(r1 + 8) * ALD + j0];
        uint32_t ah2 = s_ahi[r1 * ALD + j0 + 4];
        uint32_t ah3 = s_ahi[(r1 + 8) * ALD + j0 + 4];
        uint32_t al0 = s_alo[r1 * ALD + j0];
        uint32_t al1 = s_alo[(r1 + 8) * ALD + j0];
        uint32_t al2 = s_alo[r1 * ALD + j0 + 4];
        uint32_t al3 = s_alo[(r1 + 8) * ALD + j0 + 4];
        const uint4* bp = &g_b1frag[kc * 512 + hb * 32 + lane];
#pragma unroll
        for (int nt = 0; nt < 8; nt++) {
            uint4 bb = bp[nt * 32];
            mma16816(acc[nt], ah0, ah1, ah2, ah3, bb.x, bb.y);   // hi*Whi
            mma16816(acc[nt], ah0, ah1, ah2, ah3, bb.z, bb.w);   // hi*Wlo
            mma16816(acc[nt], al0, al1, al2, al3, bb.x, bb.y);   // lo*Whi
        }
    }

    // ---- layer 2 partial: relu(acc + hg) as A-frags over this warp's 64 h ----
    int colb = jb * 2;
    float acc2[3][4];
#pragma unroll
    for (int nt = 0; nt < 3; nt++)
#pragma unroll
        for (int j = 0; j < 4; j++) acc2[nt][j] = 0.f;

#pragma unroll
    for (int kcl = 0; kcl < 4; kcl++) {
        int kc2 = hh * 4 + kcl;
        uint32_t ah[4], al[4];
#pragma unroll
        for (int half = 0; half < 2; half++) {
            int nt = 2 * kcl + half;
            int colg = (hb + nt) * 8 + colb;
            float g0 = s_hg[colg], g1 = s_hg[colg + 1];
            float h0 = fmaxf(acc[nt][0] + g0, 0.f);
            float h1 = fmaxf(acc[nt][1] + g1, 0.f);
            float h2 = fmaxf(acc[nt][2] + g0, 0.f);
            float h3 = fmaxf(acc[nt][3] + g1, 0.f);
            ah[half ? 2 : 0] = pkbf(h0, h1);
            ah[half ? 3 : 1] = pkbf(h2, h3);
            al[half ? 2 : 0] = pkbf(bfres(h0), bfres(h1));
            al[half ? 3 : 1] = pkbf(bfres(h2), bfres(h3));
        }
        const uint4* bp = &g_b2frag[kc2 * 96 + lane];
#pragma unroll
        for (int nt = 0; nt < 3; nt++) {
            uint4 bb = bp[nt * 32];
            mma16816(acc2[nt], ah[0], ah[1], ah[2], ah[3], bb.x, bb.y);
            mma16816(acc2[nt], ah[0], ah[1], ah[2], ah[3], bb.z, bb.w);
            mma16816(acc2[nt], al[0], al[1], al[2], al[3], bb.x, bb.y);
        }
    }

    // ---- pair reduction: warp w+4 stores, warp w adds ----
    if (hh == 1) {
        float* r = &s_red[(wq * 32 + lane) * 12];
#pragma unroll
        for (int nt = 0; nt < 3; nt++)
#pragma unroll
            for (int j = 0; j < 4; j++) r[nt * 4 + j] = acc2[nt][j];
    }
    __syncthreads();

    // ---- masked epilogue (warps 0-3) ----
    if (hh == 0) {
        const float* r = &s_red[(wq * 32 + lane) * 12];
        int valA = r1 < vc, valB = (r1 + 8) < vc;
        int slotA = b * MC + r1;
#pragma unroll
        for (int nt = 0; nt < 3; nt++) {
            int m0 = nt * 8 + colb;
            float bz0 = s_b2[m0], bz1 = s_b2[m0 + 1];
            long long oA = (long long)slotA * MV + m0;
            long long oB = oA + 8 * MV;
            int kA0 = isb2 ? (mvb[oA] != 0)     : (mvi[oA] != 0);
            int kA1 = isb2 ? (mvb[oA + 1] != 0) : (mvi[oA + 1] != 0);
            int kB0 = isb2 ? (mvb[oB] != 0)     : (mvi[oB] != 0);
            int kB1 = isb2 ? (mvb[oB + 1] != 0) : (mvi[oB + 1] != 0);
            float2 vA, vB;
            vA.x = (valA && kA0) ? acc2[nt][0] + r[nt * 4 + 0] + bz0 : NEGV;
            vA.y = (valA && kA1) ? acc2[nt][1] + r[nt * 4 + 1] + bz1 : NEGV;
            vB.x = (valB && kB0) ? acc2[nt][2] + r[nt * 4 + 2] + bz0 : NEGV;
            vB.y = (valB && kB1) ? acc2[nt][3] + r[nt * 4 + 3] + bz1 : NEGV;
            *(float2*)&out[oA] = vA;
            *(float2*)&out[oB] = vB;
        }
    }
}

// ---------------------------------------------------------------------------
extern "C" void kernel_launch(void* const* d_in, const int* in_sizes, int n_in,
                              void* d_out, int out_size) {
    const float* nf = (const float*)d_in[0];
    const float* gf = (const float*)d_in[1];
    const float* W1 = (const float*)d_in[2];
    const float* b1 = (const float*)d_in[3];
    const float* W2 = (const float*)d_in[4];
    const float* b2 = (const float*)d_in[5];
    const void* cm = d_in[6];
    const int* batch = (const int*)d_in[7];
    const void* mv = d_in[8];

    int n = in_sizes[7];
    int B = in_sizes[1] / G;
    if (B > MAXB) B = MAXB;

    cudaFuncSetAttribute(k_mlp, cudaFuncAttributeMaxDynamicSharedMemorySize,
                         DSMEM_BYTES);

    k_prep<<<B + 19, 256>>>(gf, W1, b1, W2,
                            (const unsigned char*)cm, (const unsigned char*)mv,
                            batch, n, B);
    k_mlp<<<B, 256, DSMEM_BYTES>>>(
        nf, b2,
        (const unsigned char*)cm, (const int*)cm,
        (const unsigned char*)mv, (const int*)mv,
        (float*)d_out);
}

// round 11
// speedup vs baseline: 1.0036x; 1.0036x over previous
#include <cuda_runtime.h>
#include <cuda_bf16.h>
#include <stdint.h>

// ---------------------------------------------------------------------------
// CubeMoveHead R9: 3-kernel pipeline to cut the per-CTA latency chain.
//   k_pre : dtype detect + segment starts via adjacent-compare scan
//   k_prep: per-batch hg, W1/W2 HMMA fragments, per-batch select -> g_sel
//   k_mlp : gather -> 3-pass bf16 HMMA (both layers) -> masked epilogue
// ---------------------------------------------------------------------------

#define D 128
#define G 128
#define H 128
#define MC 64
#define MV 24
#define NEGV (-1000000000.0f)
#define MAXB 1024

__device__ int   g_segStart[MAXB + 1];
__device__ int   g_sel[MAXB * MC];
__device__ int   g_validCount[MAXB];
__device__ int   g_maskIsBool[2];       // [0] cube_mask, [1] move_mask
__device__ float g_hg[MAXB * H];        // gf[b] @ W1[D:,:] + b1
__device__ uint4 g_b1frag[4096];        // W1[:D,:] frags [kc8][nt16][lane32]
__device__ uint4 g_b2frag[768];         // W2 frags [kc8][nt3][lane32]

// ---------------------------------------------------------------------------
__device__ __forceinline__ uint32_t pkbf(float lo, float hi) {
    unsigned short l = __bfloat16_as_ushort(__float2bfloat16(lo));
    unsigned short h = __bfloat16_as_ushort(__float2bfloat16(hi));
    return (uint32_t)l | ((uint32_t)h << 16);
}
__device__ __forceinline__ float bfres(float x) {
    return x - __bfloat162float(__float2bfloat16(x));
}
__device__ __forceinline__ void mma16816(float* c, uint32_t a0, uint32_t a1,
                                         uint32_t a2, uint32_t a3,
                                         uint32_t b0, uint32_t b1) {
    asm volatile(
        "mma.sync.aligned.m16n8k16.row.col.f32.bf16.bf16.f32 "
        "{%0,%1,%2,%3}, {%4,%5,%6,%7}, {%8,%9}, {%0,%1,%2,%3};"
        : "+f"(c[0]), "+f"(c[1]), "+f"(c[2]), "+f"(c[3])
        : "r"(a0), "r"(a1), "r"(a2), "r"(a3), "r"(b0), "r"(b1));
}

// ---------------------------------------------------------------------------
// k_pre: boundary scan for segment starts (batch is sorted) + dtype detect.
// segStart[v] = first index i with batch[i] >= v.
// ---------------------------------------------------------------------------
__global__ __launch_bounds__(256) void k_pre(
    const int* __restrict__ batch, int n, int B,
    const unsigned char* __restrict__ cm, const unsigned char* __restrict__ mv) {
    int i = blockIdx.x * 256 + threadIdx.x;
    if (i < n) {
        int bi = batch[i];
        if (i == 0)
            for (int v = 0; v <= bi && v <= B; v++) g_segStart[v] = 0;
        if (i < n - 1) {
            int bn = batch[i + 1];
            for (int v = bi + 1; v <= bn && v <= B; v++) g_segStart[v] = i + 1;
        } else {
            for (int v = bi + 1; v <= B; v++) g_segStart[v] = n;
        }
    }
    if (blockIdx.x == 0) {
        int tid = threadIdx.x;
        int f0 = 0, f1 = 0;
        for (int j = tid; j < 4096; j += 256)
            if (j & 3) { f0 |= cm[j]; f1 |= mv[j]; }
        int r0 = __syncthreads_or(f0);
        int r1 = __syncthreads_or(f1);
        if (tid == 0) { g_maskIsBool[0] = (r0 != 0); g_maskIsBool[1] = (r1 != 0); }
    }
}

// ---------------------------------------------------------------------------
// k_prep: blocks [0,B) = per-batch select; [B,2B) = per-batch hg;
//         [2B,2B+16) = W1 frags; 2B+16 = W2 frags.
// ---------------------------------------------------------------------------
__global__ __launch_bounds__(256) void k_prep(
    const float* __restrict__ gf, const float* __restrict__ W1,
    const float* __restrict__ b1, const float* __restrict__ W2,
    const unsigned char* __restrict__ cmb, const int* __restrict__ cmi,
    int B) {
    int bid = blockIdx.x, tid = threadIdx.x;

    if (bid < B) {
        // ---- select: first MC cube nodes of batch bid ----
        int b = bid;
        int isb = g_maskIsBool[0];
        __shared__ int s_wcnt[8];
        __shared__ int s_base;
        int lane = tid & 31, w = tid >> 5;
        if (tid == 0) s_base = 0;
        __syncthreads();
        int start = g_segStart[b], end = g_segStart[b + 1];
        for (int it = start; it < end; it += 256) {
            if (s_base >= MC) break;
            int i = it + tid;
            int c = 0;
            if (i < end) c = isb ? (cmb[i] != 0) : (cmi[i] != 0);
            unsigned mm = __ballot_sync(0xffffffffu, c);
            if (lane == 0) s_wcnt[w] = __popc(mm);
            __syncthreads();
            int pre = 0, tot = 0;
#pragma unroll
            for (int ww = 0; ww < 8; ww++) {
                int v = s_wcnt[ww];
                if (ww < w) pre += v;
                tot += v;
            }
            if (c) {
                int rank = s_base + pre + __popc(mm & ((1u << lane) - 1u));
                if (rank < MC) g_sel[b * MC + rank] = i;
            }
            __syncthreads();
            if (tid == 0) s_base += tot;
            __syncthreads();
        }
        if (tid == 0) g_validCount[b] = (s_base < MC) ? s_base : MC;
    } else if (bid < 2 * B) {
        // ---- per-batch hg ----
        __shared__ float s_g[G];
        int b = bid - B;
        if (tid < G) s_g[tid] = gf[b * G + tid];
        __syncthreads();
        if (tid < H) {
            float a = b1[tid];
#pragma unroll 4
            for (int k = 0; k < G; k++)
                a = fmaf(s_g[k], W1[(D + k) * H + tid], a);
            g_hg[b * H + tid] = a;
        }
    } else {
        int rel = bid - 2 * B;
        if (rel < 16) {
            int idx = rel * 256 + tid;          // 0..4095
            int lane = idx & 31, nt = (idx >> 5) & 15, kc = idx >> 9;
            int nn = nt * 8 + (lane >> 2);
            int k0 = kc * 16 + (lane & 3) * 2;
            float w00 = W1[(k0 + 0) * H + nn], w01 = W1[(k0 + 1) * H + nn];
            float w10 = W1[(k0 + 8) * H + nn], w11 = W1[(k0 + 9) * H + nn];
            uint4 o;
            o.x = pkbf(w00, w01);
            o.y = pkbf(w10, w11);
            o.z = pkbf(bfres(w00), bfres(w01));
            o.w = pkbf(bfres(w10), bfres(w11));
            g_b1frag[idx] = o;
        } else {
            for (int idx = tid; idx < 768; idx += 256) {
                int kc = idx / 96, r = idx % 96, nt = r >> 5, lane = r & 31;
                int nn = nt * 8 + (lane >> 2);
                int k0 = kc * 16 + (lane & 3) * 2;
                float w00 = W2[(k0 + 0) * MV + nn], w01 = W2[(k0 + 1) * MV + nn];
                float w10 = W2[(k0 + 8) * MV + nn], w11 = W2[(k0 + 9) * MV + nn];
                uint4 o;
                o.x = pkbf(w00, w01);
                o.y = pkbf(w10, w11);
                o.z = pkbf(bfres(w00), bfres(w01));
                o.w = pkbf(bfres(w10), bfres(w11));
                g_b2frag[idx] = o;
            }
        }
    }
}

// ---------------------------------------------------------------------------
// k_mlp: one CTA = one batch = 64 slots, 256 threads (8 warps).
// Pure compute: gather -> layer1 HMMA -> layer2 HMMA -> masked epilogue.
// Move-mask loads issued at kernel entry, packed into one bit-register.
// ---------------------------------------------------------------------------
#define ALD 68
#define AHI_BYTES (64 * ALD * 4)  // 17408
#define DSMEM_BYTES (2 * AHI_BYTES)

__global__ __launch_bounds__(256) void k_mlp(
    const float* __restrict__ nf, const float* __restrict__ b2,
    const unsigned char* __restrict__ mvb, const int* __restrict__ mvi,
    float* __restrict__ out) {
    extern __shared__ unsigned char dsm[];
    uint32_t* s_ahi = (uint32_t*)dsm;
    uint32_t* s_alo = (uint32_t*)(dsm + AHI_BYTES);
    __shared__ float s_hg[H];
    __shared__ float s_b2[MV];
    __shared__ int   s_sel[MC];
    __shared__ int   s_vc;
    __shared__ float s_red[4 * 32 * 12];

    int tid = threadIdx.x, lane = tid & 31, w = tid >> 5;
    int b = blockIdx.x;
    int isb2 = g_maskIsBool[1];          // first load; tiny, L2-resident

    int wq = w & 3;                      // slot quarter
    int hh = w >> 2;                     // h half
    int hb = hh * 8;
    int r1 = wq * 16 + (lane >> 2);
    int jb = lane & 3;
    int colb = jb * 2;

    // small stages (independent loads)
    if (tid < H) s_hg[tid] = g_hg[b * H + tid];
    if (tid < MV) s_b2[tid] = b2[tid];
    if (tid < MC) s_sel[tid] = g_sel[b * MC + tid];
    if (tid == 0) s_vc = g_validCount[b];

    // early move-mask fetch for epilogue warps -> one packed bit register
    unsigned mmask = 0;
    if (hh == 0) {
        int slotA = b * MC + r1;
#pragma unroll
        for (int nt = 0; nt < 3; nt++) {
            long long oA = (long long)slotA * MV + nt * 8 + colb;
            long long oB = oA + 8 * MV;
            int kA0 = isb2 ? (mvb[oA] != 0)     : (mvi[oA] != 0);
            int kA1 = isb2 ? (mvb[oA + 1] != 0) : (mvi[oA + 1] != 0);
            int kB0 = isb2 ? (mvb[oB] != 0)     : (mvi[oB] != 0);
            int kB1 = isb2 ? (mvb[oB + 1] != 0) : (mvi[oB + 1] != 0);
            mmask |= (unsigned)(kA0 | (kA1 << 1) | (kB0 << 2) | (kB1 << 3)) << (nt * 4);
        }
    }
    __syncthreads();
    int vc = s_vc;

    // ---- gather node features -> packed bf16 hi/lo in smem ----
    for (int i = tid; i < 2048; i += 256) {      // 64 slots x 32 float4
        int s = i >> 5, q = i & 31;
        float4 v = make_float4(0.f, 0.f, 0.f, 0.f);
        if (s < vc) {
            long long node = s_sel[s];
            v = *(const float4*)&nf[node * D + q * 4];
        }
        uint2 hi, lo;
        hi.x = pkbf(v.x, v.y);               hi.y = pkbf(v.z, v.w);
        lo.x = pkbf(bfres(v.x), bfres(v.y)); lo.y = pkbf(bfres(v.z), bfres(v.w));
        *(uint2*)&s_ahi[s * ALD + q * 2] = hi;
        *(uint2*)&s_alo[s * ALD + q * 2] = lo;
    }
    __syncthreads();

    // ---- layer 1: warp tile = 16 slots x 64 h (3-pass bf16 HMMA) ----
    float acc[8][4];
#pragma unroll
    for (int nt = 0; nt < 8; nt++)
#pragma unroll
        for (int j = 0; j < 4; j++) acc[nt][j] = 0.f;

#pragma unroll 1
    for (int kc = 0; kc < 8; kc++) {
        int j0 = kc * 8 + jb;
        uint32_t ah0 = s_ahi[r1 * ALD + j0];
        uint32_t ah1 = s_ahi[(r1 + 8) * ALD + j0];
        uint32_t ah2 = s_ahi[r1 * ALD + j0 + 4];
        uint32_t ah3 = s_ahi[(r1 + 8) * ALD + j0 + 4];
        uint32_t al0 = s_alo[r1 * ALD + j0];
        uint32_t al1 = s_alo[(r1 + 8) * ALD + j0];
        uint32_t al2 = s_alo[r1 * ALD + j0 + 4];
        uint32_t al3 = s_alo[(r1 + 8) * ALD + j0 + 4];
        const uint4* bp = &g_b1frag[kc * 512 + hb * 32 + lane];
#pragma unroll
        for (int nt = 0; nt < 8; nt++) {
            uint4 bb = bp[nt * 32];
            mma16816(acc[nt], ah0, ah1, ah2, ah3, bb.x, bb.y);   // hi*Whi
            mma16816(acc[nt], ah0, ah1, ah2, ah3, bb.z, bb.w);   // hi*Wlo
            mma16816(acc[nt], al0, al1, al2, al3, bb.x, bb.y);   // lo*Whi
        }
    }

    // ---- layer 2 partial over this warp's 64 h ----
    float acc2[3][4];
#pragma unroll
    for (int nt = 0; nt < 3; nt++)
#pragma unroll
        for (int j = 0; j < 4; j++) acc2[nt][j] = 0.f;

#pragma unroll
    for (int kcl = 0; kcl < 4; kcl++) {
        int kc2 = hh * 4 + kcl;
        uint32_t ah[4], al[4];
#pragma unroll
        for (int half = 0; half < 2; half++) {
            int nt = 2 * kcl + half;
            int colg = (hb + nt) * 8 + colb;
            float g0 = s_hg[colg], g1 = s_hg[colg + 1];
            float h0 = fmaxf(acc[nt][0] + g0, 0.f);
            float h1 = fmaxf(acc[nt][1] + g1, 0.f);
            float h2 = fmaxf(acc[nt][2] + g0, 0.f);
            float h3 = fmaxf(acc[nt][3] + g1, 0.f);
            ah[half ? 2 : 0] = pkbf(h0, h1);
            ah[half ? 3 : 1] = pkbf(h2, h3);
            al[half ? 2 : 0] = pkbf(bfres(h0), bfres(h1));
            al[half ? 3 : 1] = pkbf(bfres(h2), bfres(h3));
        }
        const uint4* bp = &g_b2frag[kc2 * 96 + lane];
#pragma unroll
        for (int nt = 0; nt < 3; nt++) {
            uint4 bb = bp[nt * 32];
            mma16816(acc2[nt], ah[0], ah[1], ah[2], ah[3], bb.x, bb.y);
            mma16816(acc2[nt], ah[0], ah[1], ah[2], ah[3], bb.z, bb.w);
            mma16816(acc2[nt], al[0], al[1], al[2], al[3], bb.x, bb.y);
        }
    }

    // ---- pair reduction: warps 4-7 store partials ----
    if (hh == 1) {
        float* r = &s_red[(wq * 32 + lane) * 12];
#pragma unroll
        for (int nt = 0; nt < 3; nt++)
#pragma unroll
            for (int j = 0; j < 4; j++) r[nt * 4 + j] = acc2[nt][j];
    }
    __syncthreads();

    // ---- masked epilogue (warps 0-3) ----
    if (hh == 0) {
        const float* r = &s_red[(wq * 32 + lane) * 12];
        int valA = r1 < vc, valB = (r1 + 8) < vc;
        int slotA = b * MC + r1;
#pragma unroll
        for (int nt = 0; nt < 3; nt++) {
            int m0 = nt * 8 + colb;
            float bz0 = s_b2[m0], bz1 = s_b2[m0 + 1];
            long long oA = (long long)slotA * MV + m0;
            long long oB = oA + 8 * MV;
            unsigned mb = (mmask >> (nt * 4)) & 0xF;
            float2 vA, vB;
            vA.x = (valA && (mb & 1)) ? acc2[nt][0] + r[nt * 4 + 0] + bz0 : NEGV;
            vA.y = (valA && (mb & 2)) ? acc2[nt][1] + r[nt * 4 + 1] + bz1 : NEGV;
            vB.x = (valB && (mb & 4)) ? acc2[nt][2] + r[nt * 4 + 2] + bz0 : NEGV;
            vB.y = (valB && (mb & 8)) ? acc2[nt][3] + r[nt * 4 + 3] + bz1 : NEGV;
            *(float2*)&out[oA] = vA;
            *(float2*)&out[oB] = vB;
        }
    }
}

// ---------------------------------------------------------------------------
extern "C" void kernel_launch(void* const* d_in, const int* in_sizes, int n_in,
                              void* d_out, int out_size) {
    const float* nf = (const float*)d_in[0];
    const float* gf = (const float*)d_in[1];
    const float* W1 = (const float*)d_in[2];
    const float* b1 = (const float*)d_in[3];
    const float* W2 = (const float*)d_in[4];
    const float* b2 = (const float*)d_in[5];
    const void* cm = d_in[6];
    const int* batch = (const int*)d_in[7];
    const void* mv = d_in[8];

    int n = in_sizes[7];
    int B = in_sizes[1] / G;
    if (B > MAXB) B = MAXB;

    cudaFuncSetAttribute(k_mlp, cudaFuncAttributeMaxDynamicSharedMemorySize,
                         DSMEM_BYTES);

    k_pre<<<(n + 255) / 256, 256>>>(batch, n, B,
                                    (const unsigned char*)cm,
                                    (const unsigned char*)mv);
    k_prep<<<2 * B + 17, 256>>>(gf, W1, b1, W2,
                                (const unsigned char*)cm, (const int*)cm, B);
    k_mlp<<<B, 256, DSMEM_BYTES>>>(
        nf, b2,
        (const unsigned char*)mv, (const int*)mv,
        (float*)d_out);
}

// round 13
// speedup vs baseline: 1.0742x; 1.0703x over previous
#include <cuda_runtime.h>
#include <cuda_bf16.h>
#include <stdint.h>

// ---------------------------------------------------------------------------
// CubeMoveHead R11: 2-kernel pipeline.
//   k_prep: per-batch select (block-cooperative 256-ary lower_bound for the
//           segment start; strip scan self-terminates at segment end),
//           per-batch hg, W1/W2 HMMA fragments, move-mask dtype detect.
//   k_mlp : gather -> 3-pass bf16 HMMA (both layers) -> masked epilogue.
// ---------------------------------------------------------------------------

#define D 128
#define G 128
#define H 128
#define MC 64
#define MV 24
#define NEGV (-1000000000.0f)
#define MAXB 1024

__device__ int   g_sel[MAXB * MC];
__device__ int   g_validCount[MAXB];
__device__ int   g_maskIsBool[2];       // [1] move_mask (k_mlp); [0] unused
__device__ float g_hg[MAXB * H];        // gf[b] @ W1[D:,:] + b1
__device__ uint4 g_b1frag[4096];        // W1[:D,:] frags [kc8][nt16][lane32]
__device__ uint4 g_b2frag[768];         // W2 frags [kc8][nt3][lane32]

// ---------------------------------------------------------------------------
__device__ __forceinline__ uint32_t pkbf(float lo, float hi) {
    unsigned short l = __bfloat16_as_ushort(__float2bfloat16(lo));
    unsigned short h = __bfloat16_as_ushort(__float2bfloat16(hi));
    return (uint32_t)l | ((uint32_t)h << 16);
}
__device__ __forceinline__ float bfres(float x) {
    return x - __bfloat162float(__float2bfloat16(x));
}
__device__ __forceinline__ void mma16816(float* c, uint32_t a0, uint32_t a1,
                                         uint32_t a2, uint32_t a3,
                                         uint32_t b0, uint32_t b1) {
    asm volatile(
        "mma.sync.aligned.m16n8k16.row.col.f32.bf16.bf16.f32 "
        "{%0,%1,%2,%3}, {%4,%5,%6,%7}, {%8,%9}, {%0,%1,%2,%3};"
        : "+f"(c[0]), "+f"(c[1]), "+f"(c[2]), "+f"(c[3])
        : "r"(a0), "r"(a1), "r"(a2), "r"(a3), "r"(b0), "r"(b1));
}

// ---------------------------------------------------------------------------
// k_prep: blocks [0,B) = select; [B,2B) = hg; [2B,2B+16) = W1 frags;
//         2B+16 = W2 frags; 2B+17 = move-mask dtype detect.
// ---------------------------------------------------------------------------
__global__ __launch_bounds__(256) void k_prep(
    const float* __restrict__ gf, const float* __restrict__ W1,
    const float* __restrict__ b1, const float* __restrict__ W2,
    const unsigned char* __restrict__ cmb, const int* __restrict__ cmi,
    const int* __restrict__ batch, const unsigned char* __restrict__ mvb,
    int n, int B) {
    int bid = blockIdx.x, tid = threadIdx.x;

    if (bid < B) {
        // ---- cube-mask dtype self-detect (4KB, L2-shared across blocks) ----
        int f0 = 0;
        int lim = n < 4096 ? n : 4096;
        for (int j = tid; j < lim; j += 256)
            if (j & 3) f0 |= cmb[j];
        int isb = (__syncthreads_or(f0) != 0);

        // ---- block-cooperative 256-ary lower_bound(batch, n, b) ----
        int v = bid;
        int lo = 0, hi = n;
        while (hi - lo > 256) {
            long long span = hi - lo;
            int pos = lo + (int)((span * tid) >> 8);       // tid=0 -> lo
            int pred = batch[pos] < v;
            int cnt = __syncthreads_count(pred);           // monotone preds
            int nlo = cnt ? lo + (int)((span * (long long)(cnt - 1)) >> 8) : lo;
            int nhi = (cnt < 256) ? lo + (int)((span * (long long)cnt) >> 8) : hi;
            lo = nlo; hi = nhi;
        }
        {
            int pred = (lo + tid < hi) && (batch[lo + tid] < v);
            lo += __syncthreads_count(pred);               // = segment start
        }

        // ---- strip scan: first MC cubes; self-terminates at segment end ----
        __shared__ int s_wcnt[8];
        __shared__ int s_base;
        int lane = tid & 31, w = tid >> 5;
        if (tid == 0) s_base = 0;
        __syncthreads();
        for (int it = lo;; it += 256) {
            int i = it + tid;
            int bi = (i < n) ? batch[i] : 0x7fffffff;
            int m = 0;
            if (i < n) m = isb ? (cmb[i] != 0) : (cmi[i] != 0);
            int c = (bi == v) && m;
            unsigned mm = __ballot_sync(0xffffffffu, c);
            if (lane == 0) s_wcnt[w] = __popc(mm);
            int anyend = __syncthreads_or(bi > v);         // barrier: s_wcnt visible
            int pre = 0, tot = 0;
#pragma unroll
            for (int ww = 0; ww < 8; ww++) {
                int x = s_wcnt[ww];
                if (ww < w) pre += x;
                tot += x;
            }
            if (c) {
                int rank = s_base + pre + __popc(mm & ((1u << lane) - 1u));
                if (rank < MC) g_sel[v * MC + rank] = i;
            }
            __syncthreads();
            if (tid == 0) s_base += tot;
            __syncthreads();
            if (s_base >= MC || anyend) break;             // both uniform
        }
        if (tid == 0) g_validCount[v] = (s_base < MC) ? s_base : MC;
    } else if (bid < 2 * B) {
        // ---- per-batch hg ----
        __shared__ float s_g[G];
        int b = bid - B;
        if (tid < G) s_g[tid] = gf[b * G + tid];
        __syncthreads();
        if (tid < H) {
            float a = b1[tid];
#pragma unroll 4
            for (int k = 0; k < G; k++)
                a = fmaf(s_g[k], W1[(D + k) * H + tid], a);
            g_hg[b * H + tid] = a;
        }
    } else {
        int rel = bid - 2 * B;
        if (rel < 16) {
            int idx = rel * 256 + tid;          // 0..4095
            int lane = idx & 31, nt = (idx >> 5) & 15, kc = idx >> 9;
            int nn = nt * 8 + (lane >> 2);
            int k0 = kc * 16 + (lane & 3) * 2;
            float w00 = W1[(k0 + 0) * H + nn], w01 = W1[(k0 + 1) * H + nn];
            float w10 = W1[(k0 + 8) * H + nn], w11 = W1[(k0 + 9) * H + nn];
            uint4 o;
            o.x = pkbf(w00, w01);
            o.y = pkbf(w10, w11);
            o.z = pkbf(bfres(w00), bfres(w01));
            o.w = pkbf(bfres(w10), bfres(w11));
            g_b1frag[idx] = o;
        } else if (rel == 16) {
            for (int idx = tid; idx < 768; idx += 256) {
                int kc = idx / 96, r = idx % 96, nt = r >> 5, lane = r & 31;
                int nn = nt * 8 + (lane >> 2);
                int k0 = kc * 16 + (lane & 3) * 2;
                float w00 = W2[(k0 + 0) * MV + nn], w01 = W2[(k0 + 1) * MV + nn];
                float w10 = W2[(k0 + 8) * MV + nn], w11 = W2[(k0 + 9) * MV + nn];
                uint4 o;
                o.x = pkbf(w00, w01);
                o.y = pkbf(w10, w11);
                o.z = pkbf(bfres(w00), bfres(w01));
                o.w = pkbf(bfres(w10), bfres(w11));
                g_b2frag[idx] = o;
            }
        } else {
            // ---- move-mask dtype detect (for k_mlp) ----
            int f1 = 0;
            for (int j = tid; j < 4096; j += 256)
                if (j & 3) f1 |= mvb[j];
            int r1 = __syncthreads_or(f1);
            if (tid == 0) g_maskIsBool[1] = (r1 != 0);
        }
    }
}

// ---------------------------------------------------------------------------
// k_mlp: one CTA = one batch = 64 slots, 256 threads (8 warps). Unchanged
// from R9 (gather -> layer1 HMMA -> layer2 HMMA -> masked epilogue).
// ---------------------------------------------------------------------------
#define ALD 68
#define AHI_BYTES (64 * ALD * 4)  // 17408
#define DSMEM_BYTES (2 * AHI_BYTES)

__global__ __launch_bounds__(256) void k_mlp(
    const float* __restrict__ nf, const float* __restrict__ b2,
    const unsigned char* __restrict__ mvb, const int* __restrict__ mvi,
    float* __restrict__ out) {
    extern __shared__ unsigned char dsm[];
    uint32_t* s_ahi = (uint32_t*)dsm;
    uint32_t* s_alo = (uint32_t*)(dsm + AHI_BYTES);
    __shared__ float s_hg[H];
    __shared__ float s_b2[MV];
    __shared__ int   s_sel[MC];
    __shared__ int   s_vc;
    __shared__ float s_red[4 * 32 * 12];

    int tid = threadIdx.x, lane = tid & 31, w = tid >> 5;
    int b = blockIdx.x;
    int isb2 = g_maskIsBool[1];

    int wq = w & 3;
    int hh = w >> 2;
    int hb = hh * 8;
    int r1 = wq * 16 + (lane >> 2);
    int jb = lane & 3;
    int colb = jb * 2;

    if (tid < H) s_hg[tid] = g_hg[b * H + tid];
    if (tid < MV) s_b2[tid] = b2[tid];
    if (tid < MC) s_sel[tid] = g_sel[b * MC + tid];
    if (tid == 0) s_vc = g_validCount[b];

    unsigned mmask = 0;
    if (hh == 0) {
        int slotA = b * MC + r1;
#pragma unroll
        for (int nt = 0; nt < 3; nt++) {
            long long oA = (long long)slotA * MV + nt * 8 + colb;
            long long oB = oA + 8 * MV;
            int kA0 = isb2 ? (mvb[oA] != 0)     : (mvi[oA] != 0);
            int kA1 = isb2 ? (mvb[oA + 1] != 0) : (mvi[oA + 1] != 0);
            int kB0 = isb2 ? (mvb[oB] != 0)     : (mvi[oB] != 0);
            int kB1 = isb2 ? (mvb[oB + 1] != 0) : (mvi[oB + 1] != 0);
            mmask |= (unsigned)(kA0 | (kA1 << 1) | (kB0 << 2) | (kB1 << 3)) << (nt * 4);
        }
    }
    __syncthreads();
    int vc = s_vc;

    for (int i = tid; i < 2048; i += 256) {
        int s = i >> 5, q = i & 31;
        float4 v = make_float4(0.f, 0.f, 0.f, 0.f);
        if (s < vc) {
            long long node = s_sel[s];
            v = *(const float4*)&nf[node * D + q * 4];
        }
        uint2 hi, lo;
        hi.x = pkbf(v.x, v.y);               hi.y = pkbf(v.z, v.w);
        lo.x = pkbf(bfres(v.x), bfres(v.y)); lo.y = pkbf(bfres(v.z), bfres(v.w));
        *(uint2*)&s_ahi[s * ALD + q * 2] = hi;
        *(uint2*)&s_alo[s * ALD + q * 2] = lo;
    }
    __syncthreads();

    float acc[8][4];
#pragma unroll
    for (int nt = 0; nt < 8; nt++)
#pragma unroll
        for (int j = 0; j < 4; j++) acc[nt][j] = 0.f;

#pragma unroll 1
    for (int kc = 0; kc < 8; kc++) {
        int j0 = kc * 8 + jb;
        uint32_t ah0 = s_ahi[r1 * ALD + j0];
        uint32_t ah1 = s_ahi[(r1 + 8) * ALD + j0];
        uint32_t ah2 = s_ahi[r1 * ALD + j0 + 4];
        uint32_t ah3 = s_ahi[(r1 + 8) * ALD + j0 + 4];
        uint32_t al0 = s_alo[r1 * ALD + j0];
        uint32_t al1 = s_alo[(r1 + 8) * ALD + j0];
        uint32_t al2 = s_alo[r1 * ALD + j0 + 4];
        uint32_t al3 = s_alo[(r1 + 8) * ALD + j0 + 4];
        const uint4* bp = &g_b1frag[kc * 512 + hb * 32 + lane];
#pragma unroll
        for (int nt = 0; nt < 8; nt++) {
            uint4 bb = bp[nt * 32];
            mma16816(acc[nt], ah0, ah1, ah2, ah3, bb.x, bb.y);
            mma16816(acc[nt], ah0, ah1, ah2, ah3, bb.z, bb.w);
            mma16816(acc[nt], al0, al1, al2, al3, bb.x, bb.y);
        }
    }

    float acc2[3][4];
#pragma unroll
    for (int nt = 0; nt < 3; nt++)
#pragma unroll
        for (int j = 0; j < 4; j++) acc2[nt][j] = 0.f;

#pragma unroll
    for (int kcl = 0; kcl < 4; kcl++) {
        int kc2 = hh * 4 + kcl;
        uint32_t ah[4], al[4];
#pragma unroll
        for (int half = 0; half < 2; half++) {
            int nt = 2 * kcl + half;
            int colg = (hb + nt) * 8 + colb;
            float g0 = s_hg[colg], g1 = s_hg[colg + 1];
            float h0 = fmaxf(acc[nt][0] + g0, 0.f);
            float h1 = fmaxf(acc[nt][1] + g1, 0.f);
            float h2 = fmaxf(acc[nt][2] + g0, 0.f);
            float h3 = fmaxf(acc[nt][3] + g1, 0.f);
            ah[half ? 2 : 0] = pkbf(h0, h1);
            ah[half ? 3 : 1] = pkbf(h2, h3);
            al[half ? 2 : 0] = pkbf(bfres(h0), bfres(h1));
            al[half ? 3 : 1] = pkbf(bfres(h2), bfres(h3));
        }
        const uint4* bp = &g_b2frag[kc2 * 96 + lane];
#pragma unroll
        for (int nt = 0; nt < 3; nt++) {
            uint4 bb = bp[nt * 32];
            mma16816(acc2[nt], ah[0], ah[1], ah[2], ah[3], bb.x, bb.y);
            mma16816(acc2[nt], ah[0], ah[1], ah[2], ah[3], bb.z, bb.w);
            mma16816(acc2[nt], al[0], al[1], al[2], al[3], bb.x, bb.y);
        }
    }

    if (hh == 1) {
        float* r = &s_red[(wq * 32 + lane) * 12];
#pragma unroll
        for (int nt = 0; nt < 3; nt++)
#pragma unroll
            for (int j = 0; j < 4; j++) r[nt * 4 + j] = acc2[nt][j];
    }
    __syncthreads();

    if (hh == 0) {
        const float* r = &s_red[(wq * 32 + lane) * 12];
        int valA = r1 < vc, valB = (r1 + 8) < vc;
        int slotA = b * MC + r1;
#pragma unroll
        for (int nt = 0; nt < 3; nt++) {
            int m0 = nt * 8 + colb;
            float bz0 = s_b2[m0], bz1 = s_b2[m0 + 1];
            long long oA = (long long)slotA * MV + m0;
            long long oB = oA + 8 * MV;
            unsigned mb = (mmask >> (nt * 4)) & 0xF;
            float2 vA, vB;
            vA.x = (valA && (mb & 1)) ? acc2[nt][0] + r[nt * 4 + 0] + bz0 : NEGV;
            vA.y = (valA && (mb & 2)) ? acc2[nt][1] + r[nt * 4 + 1] + bz1 : NEGV;
            vB.x = (valB && (mb & 4)) ? acc2[nt][2] + r[nt * 4 + 2] + bz0 : NEGV;
            vB.y = (valB && (mb & 8)) ? acc2[nt][3] + r[nt * 4 + 3] + bz1 : NEGV;
            *(float2*)&out[oA] = vA;
            *(float2*)&out[oB] = vB;
        }
    }
}

// ---------------------------------------------------------------------------
extern "C" void kernel_launch(void* const* d_in, const int* in_sizes, int n_in,
                              void* d_out, int out_size) {
    const float* nf = (const float*)d_in[0];
    const float* gf = (const float*)d_in[1];
    const float* W1 = (const float*)d_in[2];
    const float* b1 = (const float*)d_in[3];
    const float* W2 = (const float*)d_in[4];
    const float* b2 = (const float*)d_in[5];
    const void* cm = d_in[6];
    const int* batch = (const int*)d_in[7];
    const void* mv = d_in[8];

    int n = in_sizes[7];
    int B = in_sizes[1] / G;
    if (B > MAXB) B = MAXB;

    cudaFuncSetAttribute(k_mlp, cudaFuncAttributeMaxDynamicSharedMemorySize,
                         DSMEM_BYTES);

    k_prep<<<2 * B + 18, 256>>>(gf, W1, b1, W2,
                                (const unsigned char*)cm, (const int*)cm,
                                batch, (const unsigned char*)mv, n, B);
    k_mlp<<<B, 256, DSMEM_BYTES>>>(
        nf, b2,
        (const unsigned char*)mv, (const int*)mv,
        (float*)d_out);
}

// round 16
// speedup vs baseline: 1.5714x; 1.4629x over previous
#include <cuda_runtime.h>
#include <cuda_bf16.h>
#include <stdint.h>

// ---------------------------------------------------------------------------
// CubeMoveHead R14: 2-kernel pipeline, single-pass bf16 HMMA.
//   k_prep: per-batch select (block-cooperative 256-ary lower_bound +
//           self-terminating strip scan), per-batch hg, W1/W2 HMMA fragments
//           (bf16), move-mask dtype detect.
//   k_mlp : gather -> bf16 HMMA (both layers, single pass) -> masked epilogue.
// R14 fix: ALD = 68 (64 uint32 of packed bf16 per slot + 4 pad); R13 had 36,
// overflowing the dynamic smem allocation (illegal memory access).
// ---------------------------------------------------------------------------

#define D 128
#define G 128
#define H 128
#define MC 64
#define MV 24
#define NEGV (-1000000000.0f)
#define MAXB 1024

__device__ int   g_sel[MAXB * MC];
__device__ int   g_validCount[MAXB];
__device__ int   g_maskIsBool[2];       // [1] move_mask (k_mlp)
__device__ float g_hg[MAXB * H];        // gf[b] @ W1[D:,:] + b1
__device__ uint2 g_b1frag[4096];        // W1[:D,:] frags [kc8][nt16][lane32]{b0,b1}
__device__ uint2 g_b2frag[768];         // W2 frags [kc8][nt3][lane32]

// ---------------------------------------------------------------------------
__device__ __forceinline__ uint32_t pkbf(float lo, float hi) {
    unsigned short l = __bfloat16_as_ushort(__float2bfloat16(lo));
    unsigned short h = __bfloat16_as_ushort(__float2bfloat16(hi));
    return (uint32_t)l | ((uint32_t)h << 16);
}
__device__ __forceinline__ void mma16816(float* c, uint32_t a0, uint32_t a1,
                                         uint32_t a2, uint32_t a3,
                                         uint32_t b0, uint32_t b1) {
    asm volatile(
        "mma.sync.aligned.m16n8k16.row.col.f32.bf16.bf16.f32 "
        "{%0,%1,%2,%3}, {%4,%5,%6,%7}, {%8,%9}, {%0,%1,%2,%3};"
        : "+f"(c[0]), "+f"(c[1]), "+f"(c[2]), "+f"(c[3])
        : "r"(a0), "r"(a1), "r"(a2), "r"(a3), "r"(b0), "r"(b1));
}

// ---------------------------------------------------------------------------
// k_prep: blocks [0,B) = select; [B,2B) = hg; [2B,2B+16) = W1 frags;
//         2B+16 = W2 frags; 2B+17 = move-mask dtype detect.
// ---------------------------------------------------------------------------
__global__ __launch_bounds__(256) void k_prep(
    const float* __restrict__ gf, const float* __restrict__ W1,
    const float* __restrict__ b1, const float* __restrict__ W2,
    const unsigned char* __restrict__ cmb, const int* __restrict__ cmi,
    const int* __restrict__ batch, const unsigned char* __restrict__ mvb,
    int n, int B) {
    int bid = blockIdx.x, tid = threadIdx.x;

    if (bid < B) {
        // ---- cube-mask dtype self-detect (4KB, L2-shared across blocks) ----
        int f0 = 0;
        int lim = n < 4096 ? n : 4096;
        for (int j = tid; j < lim; j += 256)
            if (j & 3) f0 |= cmb[j];
        int isb = (__syncthreads_or(f0) != 0);

        // ---- block-cooperative 256-ary lower_bound(batch, n, b) ----
        int v = bid;
        int lo = 0, hi = n;
        while (hi - lo > 256) {
            long long span = hi - lo;
            int pos = lo + (int)((span * tid) >> 8);       // tid=0 -> lo
            int pred = batch[pos] < v;
            int cnt = __syncthreads_count(pred);           // monotone preds
            int nlo = cnt ? lo + (int)((span * (long long)(cnt - 1)) >> 8) : lo;
            int nhi = (cnt < 256) ? lo + (int)((span * (long long)cnt) >> 8) : hi;
            lo = nlo; hi = nhi;
        }
        {
            int pred = (lo + tid < hi) && (batch[lo + tid] < v);
            lo += __syncthreads_count(pred);               // = segment start
        }

        // ---- strip scan: first MC cubes; self-terminates at segment end ----
        __shared__ int s_wcnt[8];
        __shared__ int s_base;
        int lane = tid & 31, w = tid >> 5;
        if (tid == 0) s_base = 0;
        __syncthreads();
        for (int it = lo;; it += 256) {
            int i = it + tid;
            int bi = (i < n) ? batch[i] : 0x7fffffff;
            int m = 0;
            if (i < n) m = isb ? (cmb[i] != 0) : (cmi[i] != 0);
            int c = (bi == v) && m;
            unsigned mm = __ballot_sync(0xffffffffu, c);
            if (lane == 0) s_wcnt[w] = __popc(mm);
            int anyend = __syncthreads_or(bi > v);         // barrier: s_wcnt visible
            int pre = 0, tot = 0;
#pragma unroll
            for (int ww = 0; ww < 8; ww++) {
                int x = s_wcnt[ww];
                if (ww < w) pre += x;
                tot += x;
            }
            if (c) {
                int rank = s_base + pre + __popc(mm & ((1u << lane) - 1u));
                if (rank < MC) g_sel[v * MC + rank] = i;
            }
            __syncthreads();
            if (tid == 0) s_base += tot;
            __syncthreads();
            if (s_base >= MC || anyend) break;             // both uniform
        }
        if (tid == 0) g_validCount[v] = (s_base < MC) ? s_base : MC;
    } else if (bid < 2 * B) {
        // ---- per-batch hg ----
        __shared__ float s_g[G];
        int b = bid - B;
        if (tid < G) s_g[tid] = gf[b * G + tid];
        __syncthreads();
        if (tid < H) {
            float a = b1[tid];
#pragma unroll 4
            for (int k = 0; k < G; k++)
                a = fmaf(s_g[k], W1[(D + k) * H + tid], a);
            g_hg[b * H + tid] = a;
        }
    } else {
        int rel = bid - 2 * B;
        if (rel < 16) {
            int idx = rel * 256 + tid;          // 0..4095
            int lane = idx & 31, nt = (idx >> 5) & 15, kc = idx >> 9;
            int nn = nt * 8 + (lane >> 2);
            int k0 = kc * 16 + (lane & 3) * 2;
            float w00 = W1[(k0 + 0) * H + nn], w01 = W1[(k0 + 1) * H + nn];
            float w10 = W1[(k0 + 8) * H + nn], w11 = W1[(k0 + 9) * H + nn];
            uint2 o;
            o.x = pkbf(w00, w01);
            o.y = pkbf(w10, w11);
            g_b1frag[idx] = o;
        } else if (rel == 16) {
            for (int idx = tid; idx < 768; idx += 256) {
                int kc = idx / 96, r = idx % 96, nt = r >> 5, lane = r & 31;
                int nn = nt * 8 + (lane >> 2);
                int k0 = kc * 16 + (lane & 3) * 2;
                float w00 = W2[(k0 + 0) * MV + nn], w01 = W2[(k0 + 1) * MV + nn];
                float w10 = W2[(k0 + 8) * MV + nn], w11 = W2[(k0 + 9) * MV + nn];
                uint2 o;
                o.x = pkbf(w00, w01);
                o.y = pkbf(w10, w11);
                g_b2frag[idx] = o;
            }
        } else {
            // ---- move-mask dtype detect (for k_mlp) ----
            int f1 = 0;
            for (int j = tid; j < 4096; j += 256)
                if (j & 3) f1 |= mvb[j];
            int r1 = __syncthreads_or(f1);
            if (tid == 0) g_maskIsBool[1] = (r1 != 0);
        }
    }
}

// ---------------------------------------------------------------------------
// k_mlp: one CTA = one batch = 64 slots, 256 threads (8 warps).
// gather -> layer1 HMMA -> layer2 HMMA -> masked epilogue, all bf16 1-pass.
// ---------------------------------------------------------------------------
#define ALD 68                      // uint32 stride per slot (64 data + 4 pad)
#define DSMEM_BYTES (64 * ALD * 4)  // 17408

__global__ __launch_bounds__(256) void k_mlp(
    const float* __restrict__ nf, const float* __restrict__ b2,
    const unsigned char* __restrict__ mvb, const int* __restrict__ mvi,
    float* __restrict__ out) {
    extern __shared__ unsigned char dsm[];
    uint32_t* s_ahi = (uint32_t*)dsm;                 // [64][ALD] bf16 pairs
    __shared__ float s_hg[H];
    __shared__ float s_b2[MV];
    __shared__ int   s_sel[MC];
    __shared__ int   s_vc;
    __shared__ float s_red[4 * 32 * 12];

    int tid = threadIdx.x, lane = tid & 31, w = tid >> 5;
    int b = blockIdx.x;
    int isb2 = g_maskIsBool[1];

    int wq = w & 3;                      // slot quarter
    int hh = w >> 2;                     // h half
    int hb = hh * 8;
    int r1 = wq * 16 + (lane >> 2);
    int jb = lane & 3;
    int colb = jb * 2;

    if (tid < H) s_hg[tid] = g_hg[b * H + tid];
    if (tid < MV) s_b2[tid] = b2[tid];
    if (tid < MC) s_sel[tid] = g_sel[b * MC + tid];
    if (tid == 0) s_vc = g_validCount[b];

    // early move-mask fetch -> one packed bit register (epilogue warps)
    unsigned mmask = 0;
    if (hh == 0) {
        int slotA = b * MC + r1;
#pragma unroll
        for (int nt = 0; nt < 3; nt++) {
            long long oA = (long long)slotA * MV + nt * 8 + colb;
            long long oB = oA + 8 * MV;
            int kA0 = isb2 ? (mvb[oA] != 0)     : (mvi[oA] != 0);
            int kA1 = isb2 ? (mvb[oA + 1] != 0) : (mvi[oA + 1] != 0);
            int kB0 = isb2 ? (mvb[oB] != 0)     : (mvi[oB] != 0);
            int kB1 = isb2 ? (mvb[oB + 1] != 0) : (mvi[oB + 1] != 0);
            mmask |= (unsigned)(kA0 | (kA1 << 1) | (kB0 << 2) | (kB1 << 3)) << (nt * 4);
        }
    }
    __syncthreads();
    int vc = s_vc;

    // ---- gather node features -> packed bf16 in smem ----
    for (int i = tid; i < 2048; i += 256) {      // 64 slots x 32 float4
        int s = i >> 5, q = i & 31;
        float4 v = make_float4(0.f, 0.f, 0.f, 0.f);
        if (s < vc) {
            long long node = s_sel[s];
            v = *(const float4*)&nf[node * D + q * 4];
        }
        uint2 hi;
        hi.x = pkbf(v.x, v.y);
        hi.y = pkbf(v.z, v.w);
        *(uint2*)&s_ahi[s * ALD + q * 2] = hi;
    }
    __syncthreads();

    // ---- layer 1: warp tile = 16 slots x 64 h (single-pass bf16 HMMA) ----
    float acc[8][4];
#pragma unroll
    for (int nt = 0; nt < 8; nt++)
#pragma unroll
        for (int j = 0; j < 4; j++) acc[nt][j] = 0.f;

#pragma unroll 1
    for (int kc = 0; kc < 8; kc++) {
        int j0 = kc * 8 + jb;
        uint32_t ah0 = s_ahi[r1 * ALD + j0];
        uint32_t ah1 = s_ahi[(r1 + 8) * ALD + j0];
        uint32_t ah2 = s_ahi[r1 * ALD + j0 + 4];
        uint32_t ah3 = s_ahi[(r1 + 8) * ALD + j0 + 4];
        const uint2* bp = &g_b1frag[kc * 512 + hb * 32 + lane];
#pragma unroll
        for (int nt = 0; nt < 8; nt++) {
            uint2 bb = bp[nt * 32];
            mma16816(acc[nt], ah0, ah1, ah2, ah3, bb.x, bb.y);
        }
    }

    // ---- layer 2 partial over this warp's 64 h ----
    float acc2[3][4];
#pragma unroll
    for (int nt = 0; nt < 3; nt++)
#pragma unroll
        for (int j = 0; j < 4; j++) acc2[nt][j] = 0.f;

#pragma unroll
    for (int kcl = 0; kcl < 4; kcl++) {
        int kc2 = hh * 4 + kcl;
        uint32_t ah[4];
#pragma unroll
        for (int half = 0; half < 2; half++) {
            int nt = 2 * kcl + half;
            int colg = (hb + nt) * 8 + colb;
            float g0 = s_hg[colg], g1 = s_hg[colg + 1];
            float h0 = fmaxf(acc[nt][0] + g0, 0.f);
            float h1 = fmaxf(acc[nt][1] + g1, 0.f);
            float h2 = fmaxf(acc[nt][2] + g0, 0.f);
            float h3 = fmaxf(acc[nt][3] + g1, 0.f);
            ah[half ? 2 : 0] = pkbf(h0, h1);
            ah[half ? 3 : 1] = pkbf(h2, h3);
        }
        const uint2* bp = &g_b2frag[kc2 * 96 + lane];
#pragma unroll
        for (int nt = 0; nt < 3; nt++) {
            uint2 bb = bp[nt * 32];
            mma16816(acc2[nt], ah[0], ah[1], ah[2], ah[3], bb.x, bb.y);
        }
    }

    // ---- pair reduction: warps 4-7 store partials ----
    if (hh == 1) {
        float* r = &s_red[(wq * 32 + lane) * 12];
#pragma unroll
        for (int nt = 0; nt < 3; nt++)
#pragma unroll
            for (int j = 0; j < 4; j++) r[nt * 4 + j] = acc2[nt][j];
    }
    __syncthreads();

    // ---- masked epilogue (warps 0-3) ----
    if (hh == 0) {
        const float* r = &s_red[(wq * 32 + lane) * 12];
        int valA = r1 < vc, valB = (r1 + 8) < vc;
        int slotA = b * MC + r1;
#pragma unroll
        for (int nt = 0; nt < 3; nt++) {
            int m0 = nt * 8 + colb;
            float bz0 = s_b2[m0], bz1 = s_b2[m0 + 1];
            long long oA = (long long)slotA * MV + m0;
            long long oB = oA + 8 * MV;
            unsigned mb = (mmask >> (nt * 4)) & 0xF;
            float2 vA, vB;
            vA.x = (valA && (mb & 1)) ? acc2[nt][0] + r[nt * 4 + 0] + bz0 : NEGV;
            vA.y = (valA && (mb & 2)) ? acc2[nt][1] + r[nt * 4 + 1] + bz1 : NEGV;
            vB.x = (valB && (mb & 4)) ? acc2[nt][2] + r[nt * 4 + 2] + bz0 : NEGV;
            vB.y = (valB && (mb & 8)) ? acc2[nt][3] + r[nt * 4 + 3] + bz1 : NEGV;
            *(float2*)&out[oA] = vA;
            *(float2*)&out[oB] = vB;
        }
    }
}

// ---------------------------------------------------------------------------
extern "C" void kernel_launch(void* const* d_in, const int* in_sizes, int n_in,
                              void* d_out, int out_size) {
    const float* nf = (const float*)d_in[0];
    const float* gf = (const float*)d_in[1];
    const float* W1 = (const float*)d_in[2];
    const float* b1 = (const float*)d_in[3];
    const float* W2 = (const float*)d_in[4];
    const float* b2 = (const float*)d_in[5];
    const void* cm = d_in[6];
    const int* batch = (const int*)d_in[7];
    const void* mv = d_in[8];

    int n = in_sizes[7];
    int B = in_sizes[1] / G;
    if (B > MAXB) B = MAXB;

    cudaFuncSetAttribute(k_mlp, cudaFuncAttributeMaxDynamicSharedMemorySize,
                         DSMEM_BYTES);

    k_prep<<<2 * B + 18, 256>>>(gf, W1, b1, W2,
                                (const unsigned char*)cm, (const int*)cm,
                                batch, (const unsigned char*)mv, n, B);
    k_mlp<<<B, 256, DSMEM_BYTES>>>(
        nf, b2,
        (const unsigned char*)mv, (const int*)mv,
        (float*)d_out);
}